// round 17
// baseline (speedup 1.0000x reference)
#include <cuda_runtime.h>
#include <cstdint>

// AR(3), 2 dims, diagonal alpha. 4096 trials x 8192 steps.
// One block per trial, 4 tiles of 2048 noise steps, SEG=8, dims fused.
// ALL 256 threads now run phases B and C (256 segments of 8 steps), halving
// the wall time of the two heaviest phases vs the SEG=16/128-thread version.
// Double-buffered cp.async pipeline and precomputed per-lane prefix matrices
// retained from the 111.1us kernel.
//   B: 8 x LDS.64: zero-init dual-chain run -> 6-float offset b  (256 thr)
//   scan: uniform-matrix affine scan (shuffle b only; per-dim A^(8*2^k))
//   chain: tid0 serial warp-total composition, 8 warps (A^256 uniform)
//   per-lane: v = swP[d][lane] * warp_start  (precomputed A^(8*lane))
//   C: re-run both chains from true states, in-place (256 thr)
//   D: coalesced float2 flush -> out
// Tail zero-filled via cp.async src-size=0 -> branchless fixed loops.

#define TRIALS 4096
#define STEPS  8192
#define NNOISE (STEPS - 3)     // 8189
#define TILE   2048
#define NTILES 4               // 3 x 2048 + 2045 (zero-padded)
#define SEG    8
#define NSEG   256
#define NTH    256
#define PITCH  9               // float2 per segment (8 + 1 pad): 18-word rows
#define BUFSZ  (NSEG * PITCH)  // 2304 float2 per buffer

__device__ __forceinline__ void cp_async8(uint32_t dst, const void* src, int sz) {
    asm volatile("cp.async.ca.shared.global [%0], [%1], 8, %2;"
                 :: "r"(dst), "l"(src), "r"(sz));
}

__global__ __launch_bounds__(NTH, 5)
void arma_scan(const float* __restrict__ alpha, const float* __restrict__ xmu,
               const float* __restrict__ sigma, const float* __restrict__ rho_p,
               const float* __restrict__ mu,    const float* __restrict__ x_0,
               const float* __restrict__ normals, float* __restrict__ out)
{
    __shared__ float2 smv[2 * BUFSZ];        // 2 x 18432 B = 36.9 KB
    __shared__ float  swL[2][6][9];          // per-dim A^(8*2^k), k=0..5
    __shared__ float  swP[2][32][9];         // per-dim A^(8*lane), lane=0..31
    __shared__ float  swb[8][6];             // warp-total offsets
    __shared__ float  sst[8][6];             // warp start states

    const int tid  = threadIdx.x;
    const int lane = tid & 31;
    const int wd   = tid >> 5;               // warp 0..7
    const int tr   = blockIdx.x;

    // ---- parameters ----
    const float s0v = sigma[0], s1v = sigma[1];
    const float rho = rho_p[0];
    const float c10 = rho * s1v;
    const float c11 = sqrtf(1.0f - rho * rho) * s1v;
    const float k0  = mu[0] + xmu[0] * (1.0f - alpha[0] - alpha[2] - alpha[4]);
    const float k1  = mu[1] + xmu[1] * (1.0f - alpha[1] - alpha[3] - alpha[5]);
    const float p0 = alpha[0], p1 = alpha[2], p2 = alpha[4];   // dim 0
    const float q0 = alpha[1], q1 = alpha[3], q2 = alpha[5];   // dim 1

    const float2* nsrc = (const float2*)normals + (size_t)tr * NNOISE;
    float2*       odst = (float2*)out + (size_t)tr * STEPS;
    const uint32_t sbase = (uint32_t)__cvta_generic_to_shared(smv);

    // ---- preload tile 0 immediately (lands under init compute) ----
    {
        #pragma unroll
        for (int k = 0; k < TILE / NTH; ++k) {
            const int s = tid + k * NTH;
            cp_async8(sbase + (uint32_t)(((s >> 3) * PITCH + (s & 7)) * 8),
                      nsrc + s, 8);
        }
        asm volatile("cp.async.commit_group;");
    }

    // first ORDER outputs = x_0 verbatim
    if (tid < 6) out[(size_t)tr * STEPS * 2 + tid] = x_0[tr * 6 + tid];

    // ---- one-time: level matrices A^(8*2^k) for dim = tid (threads 0,1) ----
    if (tid < 2) {
        const float a0 = alpha[0 + tid], a1 = alpha[2 + tid], a2 = alpha[4 + tid];
        float m0=1,m1=0,m2=0, m3=0,m4=1,m5=0, m6=0,m7=0,m8=1;
        #pragma unroll
        for (int j = 0; j < SEG; ++j) {
            float r0 = fmaf(a0, m0, fmaf(a1, m3, a2 * m6));
            float r1 = fmaf(a0, m1, fmaf(a1, m4, a2 * m7));
            float r2 = fmaf(a0, m2, fmaf(a1, m5, a2 * m8));
            m0=m3; m1=m4; m2=m5;  m3=m6; m4=m7; m5=m8;  m6=r0; m7=r1; m8=r2;
        }
        float* L = swL[tid][0];
        L[0]=m0; L[1]=m1; L[2]=m2; L[3]=m3; L[4]=m4; L[5]=m5; L[6]=m6; L[7]=m7; L[8]=m8;
        #pragma unroll
        for (int k = 1; k < 6; ++k) {
            float c0 = fmaf(m0,m0, fmaf(m1,m3, m2*m6));
            float c1 = fmaf(m0,m1, fmaf(m1,m4, m2*m7));
            float c2 = fmaf(m0,m2, fmaf(m1,m5, m2*m8));
            float c3 = fmaf(m3,m0, fmaf(m4,m3, m5*m6));
            float c4 = fmaf(m3,m1, fmaf(m4,m4, m5*m7));
            float c5 = fmaf(m3,m2, fmaf(m4,m5, m5*m8));
            float c6 = fmaf(m6,m0, fmaf(m7,m3, m8*m6));
            float c7 = fmaf(m6,m1, fmaf(m7,m4, m8*m7));
            float c8 = fmaf(m6,m2, fmaf(m7,m5, m8*m8));
            m0=c0; m1=c1; m2=c2; m3=c3; m4=c4; m5=c5; m6=c6; m7=c7; m8=c8;
            float* Lk = swL[tid][k];
            Lk[0]=m0; Lk[1]=m1; Lk[2]=m2; Lk[3]=m3; Lk[4]=m4;
            Lk[5]=m5; Lk[6]=m6; Lk[7]=m7; Lk[8]=m8;
        }
    }
    __syncthreads();    // swL visible

    // ---- one-time: per-lane matrices A^(8*l) (threads 0..63) ----
    if (tid < 64) {
        const int d = tid >> 5, l = tid & 31;
        float m0=1,m1=0,m2=0, m3=0,m4=1,m5=0, m6=0,m7=0,m8=1;
        #pragma unroll
        for (int k = 0; k < 5; ++k) {
            if (l & (1 << k)) {
                const float* L = swL[d][k];
                float c0 = fmaf(L[0],m0, fmaf(L[1],m3, L[2]*m6));
                float c1 = fmaf(L[0],m1, fmaf(L[1],m4, L[2]*m7));
                float c2 = fmaf(L[0],m2, fmaf(L[1],m5, L[2]*m8));
                float c3 = fmaf(L[3],m0, fmaf(L[4],m3, L[5]*m6));
                float c4 = fmaf(L[3],m1, fmaf(L[4],m4, L[5]*m7));
                float c5 = fmaf(L[3],m2, fmaf(L[4],m5, L[5]*m8));
                float c6 = fmaf(L[6],m0, fmaf(L[7],m3, L[8]*m6));
                float c7 = fmaf(L[6],m1, fmaf(L[7],m4, L[8]*m7));
                float c8 = fmaf(L[6],m2, fmaf(L[7],m5, L[8]*m8));
                m0=c0; m1=c1; m2=c2; m3=c3; m4=c4; m5=c5; m6=c6; m7=c7; m8=c8;
            }
        }
        float* P = swP[d][l];
        P[0]=m0; P[1]=m1; P[2]=m2; P[3]=m3; P[4]=m4; P[5]=m5; P[6]=m6; P[7]=m7; P[8]=m8;
    }

    // per-block serial carry (tid==0)
    float cs0=0.f, cs1=0.f, cs2=0.f, cs3=0.f, cs4=0.f, cs5=0.f;
    if (tid == 0) {
        cs0 = x_0[tr*6 + 0]; cs1 = x_0[tr*6 + 2]; cs2 = x_0[tr*6 + 4];  // d0
        cs3 = x_0[tr*6 + 1]; cs4 = x_0[tr*6 + 3]; cs5 = x_0[tr*6 + 5];  // d1
    }

    #pragma unroll
    for (int h = 0; h < NTILES; ++h) {
        const int tbase = h * TILE;
        float2* buf = smv + (h & 1) * BUFSZ;

        asm volatile("cp.async.wait_group 0;");
        __syncthreads();                      // S1: tile h resident for all

        // ---- issue next tile's async copy (overlaps B/scan/C/D) ----
        if (h + 1 < NTILES) {
            const int gbase = (h + 1) * TILE;
            const uint32_t dbase = sbase + (uint32_t)(((h + 1) & 1) * BUFSZ * 8);
            if (h + 1 < NTILES - 1) {
                #pragma unroll
                for (int k = 0; k < TILE / NTH; ++k) {
                    const int s = tid + k * NTH;
                    cp_async8(dbase + (uint32_t)(((s >> 3) * PITCH + (s & 7)) * 8),
                              nsrc + gbase + s, 8);
                }
            } else {
                const int nh = NNOISE - gbase;            // 2045
                #pragma unroll
                for (int k = 0; k < TILE / NTH; ++k) {
                    const int s = tid + k * NTH;
                    const bool ok = s < nh;
                    cp_async8(dbase + (uint32_t)(((s >> 3) * PITCH + (s & 7)) * 8),
                              ok ? (nsrc + gbase + s) : nsrc, ok ? 8 : 0);
                }
            }
            asm volatile("cp.async.commit_group;");
        }

        // ---- phase B: zero-init dual-chain run on raw noise (ALL threads) ----
        float b0=0.f,b1=0.f,b2=0.f, b3=0.f,b4=0.f,b5=0.f;
        {
            const float2* np = buf + tid * PITCH;
            #pragma unroll
            for (int j = 0; j < SEG; ++j) {
                float2 rn = np[j];
                float e0 = fmaf(s0v, rn.x, k0);
                float e1 = fmaf(c10, rn.x, fmaf(c11, rn.y, k1));
                float x = fmaf(p2, b2, fmaf(p1, b1, fmaf(p0, b0, e0)));
                float y = fmaf(q2, b5, fmaf(q1, b4, fmaf(q0, b3, e1)));
                b0 = b1; b1 = b2; b2 = x;
                b3 = b4; b4 = b5; b5 = y;
            }

            // ---- uniform-matrix inclusive b-scan (all 8 warps) ----
            #pragma unroll
            for (int k = 0; k < 5; ++k) {
                const int sh = 1 << k;
                float pb0 = __shfl_up_sync(0xffffffffu, b0, sh);
                float pb1 = __shfl_up_sync(0xffffffffu, b1, sh);
                float pb2 = __shfl_up_sync(0xffffffffu, b2, sh);
                float pb3 = __shfl_up_sync(0xffffffffu, b3, sh);
                float pb4 = __shfl_up_sync(0xffffffffu, b4, sh);
                float pb5 = __shfl_up_sync(0xffffffffu, b5, sh);
                if (lane >= sh) {
                    const float* L0 = swL[0][k];
                    const float* L1 = swL[1][k];
                    b0 = fmaf(L0[0], pb0, fmaf(L0[1], pb1, fmaf(L0[2], pb2, b0)));
                    b1 = fmaf(L0[3], pb0, fmaf(L0[4], pb1, fmaf(L0[5], pb2, b1)));
                    b2 = fmaf(L0[6], pb0, fmaf(L0[7], pb1, fmaf(L0[8], pb2, b2)));
                    b3 = fmaf(L1[0], pb3, fmaf(L1[1], pb4, fmaf(L1[2], pb5, b3)));
                    b4 = fmaf(L1[3], pb3, fmaf(L1[4], pb4, fmaf(L1[5], pb5, b4)));
                    b5 = fmaf(L1[6], pb3, fmaf(L1[7], pb4, fmaf(L1[8], pb5, b5)));
                }
            }
            if (lane == 31) {
                float* bw = swb[wd];
                bw[0]=b0; bw[1]=b1; bw[2]=b2; bw[3]=b3; bw[4]=b4; bw[5]=b5;
            }
        }
        __syncthreads();                      // S2: swb visible

        // ---- serial warp-total chain (tid==0, A^256 per dim, 8 warps) ----
        if (tid == 0) {
            const float* L50 = swL[0][5];
            const float* L51 = swL[1][5];
            float t0=cs0,t1=cs1,t2=cs2, t3=cs3,t4=cs4,t5=cs5;
            #pragma unroll
            for (int w = 0; w < 8; ++w) {
                float* st = sst[w];
                st[0]=t0; st[1]=t1; st[2]=t2; st[3]=t3; st[4]=t4; st[5]=t5;
                const float* bw = swb[w];
                float u0 = fmaf(L50[0],t0, fmaf(L50[1],t1, fmaf(L50[2],t2, bw[0])));
                float u1 = fmaf(L50[3],t0, fmaf(L50[4],t1, fmaf(L50[5],t2, bw[1])));
                float u2 = fmaf(L50[6],t0, fmaf(L50[7],t1, fmaf(L50[8],t2, bw[2])));
                float u3 = fmaf(L51[0],t3, fmaf(L51[1],t4, fmaf(L51[2],t5, bw[3])));
                float u4 = fmaf(L51[3],t3, fmaf(L51[4],t4, fmaf(L51[5],t5, bw[4])));
                float u5 = fmaf(L51[6],t3, fmaf(L51[7],t4, fmaf(L51[8],t5, bw[5])));
                t0=u0; t1=u1; t2=u2; t3=u3; t4=u4; t5=u5;
            }
            cs0=t0; cs1=t1; cs2=t2; cs3=t3; cs4=t4; cs5=t5;   // carry
        }
        __syncthreads();                      // S3

        {
            // ---- per-lane start: single precomputed mat-vec + exclusive b ----
            const float* st = sst[wd];
            const float w0 = st[0], w1 = st[1], w2 = st[2];
            const float w3 = st[3], w4 = st[4], w5 = st[5];
            const float* P0 = swP[0][lane];
            const float* P1 = swP[1][lane];
            float v0 = fmaf(P0[0],w0, fmaf(P0[1],w1, P0[2]*w2));
            float v1 = fmaf(P0[3],w0, fmaf(P0[4],w1, P0[5]*w2));
            float v2 = fmaf(P0[6],w0, fmaf(P0[7],w1, P0[8]*w2));
            float v3 = fmaf(P1[0],w3, fmaf(P1[1],w4, P1[2]*w5));
            float v4 = fmaf(P1[3],w3, fmaf(P1[4],w4, P1[5]*w5));
            float v5 = fmaf(P1[6],w3, fmaf(P1[7],w4, P1[8]*w5));

            float pb0 = __shfl_up_sync(0xffffffffu, b0, 1);
            float pb1 = __shfl_up_sync(0xffffffffu, b1, 1);
            float pb2 = __shfl_up_sync(0xffffffffu, b2, 1);
            float pb3 = __shfl_up_sync(0xffffffffu, b3, 1);
            float pb4 = __shfl_up_sync(0xffffffffu, b4, 1);
            float pb5 = __shfl_up_sync(0xffffffffu, b5, 1);
            float s0 = lane ? (v0 + pb0) : v0;
            float s1 = lane ? (v1 + pb1) : v1;
            float s2 = lane ? (v2 + pb2) : v2;
            float s3 = lane ? (v3 + pb3) : v3;
            float s4 = lane ? (v4 + pb4) : v4;
            float s5 = lane ? (v5 + pb5) : v5;

            // ---- phase C: re-run from true state; overwrite raw with x ----
            float2* wp = buf + tid * PITCH;
            #pragma unroll
            for (int j = 0; j < SEG; ++j) {
                float2 rn = wp[j];
                float e0 = fmaf(s0v, rn.x, k0);
                float e1 = fmaf(c10, rn.x, fmaf(c11, rn.y, k1));
                float x = fmaf(p2, s2, fmaf(p1, s1, fmaf(p0, s0, e0)));
                float y = fmaf(q2, s5, fmaf(q1, s4, fmaf(q0, s3, e1)));
                wp[j] = make_float2(x, y);
                s0 = s1; s1 = s2; s2 = x;
                s3 = s4; s4 = s5; s5 = y;
            }
        }
        __syncthreads();                      // S4

        // ---- phase D: coalesced float2 flush -> out (t = tbase + 3 + s) ----
        if (h < NTILES - 1) {
            #pragma unroll
            for (int k = 0; k < TILE / NTH; ++k) {
                const int s = tid + k * NTH;
                odst[tbase + 3 + s] = buf[(s >> 3) * PITCH + (s & 7)];
            }
        } else {
            const int nh = NNOISE - tbase;
            #pragma unroll
            for (int k = 0; k < TILE / NTH; ++k) {
                const int s = tid + k * NTH;
                if (s < nh)
                    odst[tbase + 3 + s] = buf[(s >> 3) * PITCH + (s & 7)];
            }
        }
        // no trailing barrier: next iteration's S1 separates D from buffer reuse
    }
}

extern "C" void kernel_launch(void* const* d_in, const int* in_sizes, int n_in,
                              void* d_out, int out_size)
{
    const float* alpha   = (const float*)d_in[0];
    const float* xmu     = (const float*)d_in[1];
    const float* sigma   = (const float*)d_in[2];
    const float* rho     = (const float*)d_in[3];
    const float* mu      = (const float*)d_in[4];
    const float* x_0     = (const float*)d_in[5];
    const float* normals = (const float*)d_in[6];
    float* out = (float*)d_out;

    arma_scan<<<TRIALS, NTH>>>(alpha, xmu, sigma, rho, mu, x_0, normals, out);
}